// round 11
// baseline (speedup 1.0000x reference)
#include <cuda_runtime.h>
#include <cuda_fp16.h>
#include <cstdint>
#include <cmath>

// Problem constants
#define BATCH 8
#define CHN 3
#define IMG 224
#define HP 112      // Hp = Wp = 112
#define FIN 12      // patch features
#define D 128       // hidden per direction
#define L 112       // scan length (both stages)
#define NSEQ 896    // Hp*B = Wp*B
#define M_TOT (L * NSEQ)   // 100352

// Scratch (device globals — no dynamic allocation allowed)
__device__ __half g_a2h[(size_t)M_TOT * 256];   // stage-1 out (half): GEMM A + k3 xprime
__device__ __half g_w2t[(size_t)768 * 256];     // W2 transposed+permuted [j*256+ch][k], half
__device__ __half g_u2h[(size_t)M_TOT * 768];   // GEMM out, cols j*256+ch (j-major)

__device__ __forceinline__ float sigmoidf_(float v) {
    float t;
    asm("tanh.approx.f32 %0, %1;" : "=f"(t) : "f"(v * 0.5f));
    return fmaf(t, 0.5f, 0.5f);
}

typedef unsigned long long u64t;
__device__ __forceinline__ u64t pack2(float a, float b) {
    u64t r; asm("mov.b64 %0,{%1,%2};" : "=l"(r) : "f"(a), "f"(b)); return r;
}
__device__ __forceinline__ u64t fma2(u64t a, u64t b, u64t c) {
    u64t d; asm("fma.rn.f32x2 %0,%1,%2,%3;" : "=l"(d) : "l"(a), "l"(b), "l"(c)); return d;
}
__device__ __forceinline__ void unpack2(u64t v, float& a, float& b) {
    asm("mov.b64 {%0,%1},%2;" : "=f"(a), "=f"(b) : "l"(v));
}

#define LDSM4(r0, r1, r2, r3, addr) \
    asm volatile("ldmatrix.sync.aligned.m8n8.x4.shared.b16 {%0,%1,%2,%3},[%4];" \
                 : "=r"(r0), "=r"(r1), "=r"(r2), "=r"(r3) : "r"(addr))
#define CP16(sm, gp) \
    asm volatile("cp.async.cg.shared.global [%0], [%1], 16;" :: "r"(sm), "l"(gp))
#define CP_COMMIT() asm volatile("cp.async.commit_group;")
#define CP_WAIT1()  asm volatile("cp.async.wait_group 1;")
#define CP_WAIT0()  asm volatile("cp.async.wait_group 0;")

// ---------------------------------------------------------------------------
// Kernel 0: W2[k][n] (256x768 f32) -> g_w2t[n'][k] half, n' = (n%3)*256 + n/3
// ---------------------------------------------------------------------------
__global__ void __launch_bounds__(256) k0_w2half(const float* __restrict__ W2)
{
    const int idx = blockIdx.x * 256 + threadIdx.x;  // k*768 + n
    const int k = idx / 768;
    const int n = idx % 768;
    const int np = (n % 3) * 256 + n / 3;
    g_w2t[(size_t)np * 256 + k] = __float2half(W2[idx]);
}

// ---------------------------------------------------------------------------
// Kernel 1: fused patch-extract + (x @ W1) + bidirectional SRU scan (k=4)
// Per-warp smem packed-broadcast (double buffer, 1 syncwarp/step).
// ---------------------------------------------------------------------------
__global__ void __launch_bounds__(128) k1_scan1(
    const float* __restrict__ x, const float* __restrict__ W1,
    const float* __restrict__ wc1, const float* __restrict__ b1)
{
    const int n1  = blockIdx.x;        // hp*8 + b
    const int dir = blockIdx.y;
    const int d   = threadIdx.x;       // 0..127 (output channel)
    const int lid = d & 31;
    const int w   = d >> 5;            // warp id
    const int hp  = n1 >> 3;
    const int b   = n1 & 7;

    u64t w01[FIN], w23[FIN];
    const int col0 = (dir * D + d) * 4;
#pragma unroll
    for (int f = 0; f < FIN; f++) {
        const float* wr = W1 + f * 1024 + col0;
        w01[f] = pack2(wr[0], wr[1]);
        w23[f] = pack2(wr[2], wr[3]);
    }
    const int chg = dir * D + d;
    const float vf = wc1[chg];
    const float vr = wc1[256 + chg];
    const float bf = b1[chg];
    const float br = b1[256 + chg];

    const int l0 = dir ? (L - 1) : 0;
    const int dl = dir ? -1 : 1;

    __shared__ u64t spk[4][2][FIN];

    int xrowbase = 0, xww = 0;
    float nv = 0.0f;
    if (lid < FIN) {
        int c  = lid >> 2;
        int wh = (lid >> 1) & 1;
        xww    = lid & 1;
        xrowbase = ((b * 3 + c) * IMG + 2 * hp + wh) * IMG;
        const float v0 = x[xrowbase + 2 * l0 + xww];
        spk[w][0][lid] = pack2(v0, v0);
        nv = x[xrowbase + 2 * (l0 + dl) + xww];   // step 1 (L>1 always)
    }
    __syncwarp();

    size_t oidx = ((size_t)hp * NSEQ + l0 * 8 + b) * 256 + chg;
    const ptrdiff_t ostep = (ptrdiff_t)dl * 8 * 256;

    float cst = 0.0f;
    for (int s = 0; s < L; s++) {
        const int cur = s & 1;
        if (lid < FIN && (s + 1) < L) {
            spk[w][cur ^ 1][lid] = pack2(nv, nv);
            if ((s + 2) < L) nv = x[xrowbase + 2 * (l0 + dl * (s + 2)) + xww];
        }
        u64t acc01 = 0ull, acc23 = 0ull;
#pragma unroll
        for (int f = 0; f < FIN; f++) {
            const u64t pp = spk[w][cur][f];
            acc01 = fma2(pp, w01[f], acc01);
            acc23 = fma2(pp, w23[f], acc23);
        }
        float u0, u1, u2, u3;
        unpack2(acc01, u0, u1);
        unpack2(acc23, u2, u3);
        const float fg = sigmoidf_(u1 + vf * cst + bf);
        cst = fg * (cst - u0) + u0;
        const float rg = sigmoidf_(u2 + vr * cst + br);
        const float h  = rg * (cst - u3) + u3;
        g_a2h[oidx] = __float2half(h);
        oidx += ostep;
        __syncwarp();
    }
}

// ---------------------------------------------------------------------------
// Kernel 2: fp16 GEMM  U2[100352,768] = a2h @ w2t^T
// BM=128, BN=128, BK=32; 256 threads; warp tile 32x64; ldmatrix + m16n8k16.
// cp.async 3-stage pipeline (dynamic smem, 60KB). [R8 config — HMMA wall]
// ---------------------------------------------------------------------------
#define SAH 40                      // halves per smem row (80B, LDSM conflict-free)
#define STGB (128 * SAH * 2)        // bytes per stage per matrix (10240)
__global__ void __launch_bounds__(256, 2) k2_gemm_f16()
{
    extern __shared__ char k2smem[];
    __half* As = (__half*)k2smem;                 // 3 stages
    __half* Bs = (__half*)(k2smem + 3 * STGB);    // 3 stages

    const int tid  = threadIdx.x;
    const int lane = tid & 31;
    const int gid  = lane >> 2;     // 0..7
    const int tig  = lane & 3;      // 0..3
    const int warp = tid >> 5;
    const int wm   = (warp & 3) * 32;   // warp m offset
    const int wn   = (warp >> 2) * 64;  // warp n offset
    const int n0   = blockIdx.x * 128;
    const int m0   = blockIdx.y * 128;

    const int row = tid >> 1;           // 0..127
    const int kc  = (tid & 1) * 16;     // half-offset within 32-wide ktile

    const __half* Ag = g_a2h + (size_t)(m0 + row) * 256 + kc;
    const __half* Bg = g_w2t + (size_t)(n0 + row) * 256 + kc;

    const unsigned sa = (unsigned)__cvta_generic_to_shared(As + row * SAH + kc);
    const unsigned sb = (unsigned)__cvta_generic_to_shared(Bs + row * SAH + kc);

    // ldmatrix base addresses (stage 0, kk = 0)
    const unsigned aAddr = (unsigned)__cvta_generic_to_shared(As)
        + (((wm + (lane & 7) + (lane & 8)) * SAH + ((lane & 16) ? 8 : 0)) * 2);
    const unsigned bAddr = (unsigned)__cvta_generic_to_shared(Bs)
        + (((wn + (lane & 7) + ((lane & 16) ? 8 : 0)) * SAH + ((lane & 8) ? 8 : 0)) * 2);

    // prologue: stages 0,1 (ktiles 0,1)
#pragma unroll
    for (int s = 0; s < 2; s++) {
        CP16(sa + s * STGB,      Ag + s * 32);
        CP16(sa + s * STGB + 16, Ag + s * 32 + 8);
        CP16(sb + s * STGB,      Bg + s * 32);
        CP16(sb + s * STGB + 16, Bg + s * 32 + 8);
        CP_COMMIT();
    }

    float c[2][8][4];
#pragma unroll
    for (int mi = 0; mi < 2; mi++)
#pragma unroll
        for (int ni = 0; ni < 8; ni++)
#pragma unroll
            for (int j = 0; j < 4; j++) c[mi][ni][j] = 0.f;

    for (int kt = 0; kt < 8; kt++) {
        if (kt == 7) { CP_WAIT0(); } else { CP_WAIT1(); }
        __syncthreads();

        if (kt < 6) {
            const int s  = (kt + 2) % 3;
            const int k0 = (kt + 2) * 32;
            CP16(sa + s * STGB,      Ag + k0);
            CP16(sa + s * STGB + 16, Ag + k0 + 8);
            CP16(sb + s * STGB,      Bg + k0);
            CP16(sb + s * STGB + 16, Bg + k0 + 8);
            CP_COMMIT();
        }

        const unsigned aB = aAddr + (kt % 3) * STGB;
        const unsigned bB = bAddr + (kt % 3) * STGB;
#pragma unroll
        for (int kk = 0; kk < 32; kk += 16) {
            unsigned a[2][4];
#pragma unroll
            for (int mi = 0; mi < 2; mi++)
                LDSM4(a[mi][0], a[mi][1], a[mi][2], a[mi][3],
                      aB + mi * (16 * SAH * 2) + kk * 2);
#pragma unroll
            for (int nt = 0; nt < 4; nt++) {
                unsigned b00, b01, b10, b11;
                LDSM4(b00, b01, b10, b11, bB + nt * (16 * SAH * 2) + kk * 2);
#pragma unroll
                for (int mi = 0; mi < 2; mi++) {
                    asm volatile(
                        "mma.sync.aligned.m16n8k16.row.col.f32.f16.f16.f32 "
                        "{%0,%1,%2,%3}, {%4,%5,%6,%7}, {%8,%9}, {%0,%1,%2,%3};"
                        : "+f"(c[mi][2 * nt][0]), "+f"(c[mi][2 * nt][1]),
                          "+f"(c[mi][2 * nt][2]), "+f"(c[mi][2 * nt][3])
                        : "r"(a[mi][0]), "r"(a[mi][1]), "r"(a[mi][2]), "r"(a[mi][3]),
                          "r"(b00), "r"(b01));
                    asm volatile(
                        "mma.sync.aligned.m16n8k16.row.col.f32.f16.f16.f32 "
                        "{%0,%1,%2,%3}, {%4,%5,%6,%7}, {%8,%9}, {%0,%1,%2,%3};"
                        : "+f"(c[mi][2 * nt + 1][0]), "+f"(c[mi][2 * nt + 1][1]),
                          "+f"(c[mi][2 * nt + 1][2]), "+f"(c[mi][2 * nt + 1][3])
                        : "r"(a[mi][0]), "r"(a[mi][1]), "r"(a[mi][2]), "r"(a[mi][3]),
                          "r"(b10), "r"(b11));
                }
            }
        }
    }

#pragma unroll
    for (int mi = 0; mi < 2; mi++) {
#pragma unroll
        for (int ni = 0; ni < 8; ni++) {
            const int r0  = m0 + wm + mi * 16 + gid;
            const int col = n0 + wn + ni * 8 + tig * 2;
            *(__half2*)(g_u2h + (size_t)r0 * 768 + col) =
                __floats2half2_rn(c[mi][ni][0], c[mi][ni][1]);
            *(__half2*)(g_u2h + (size_t)(r0 + 8) * 768 + col) =
                __floats2half2_rn(c[mi][ni][2], c[mi][ni][3]);
        }
    }
}

// ---------------------------------------------------------------------------
// Kernel 3: bidirectional SRU scan (k=3) + coalesced output.
// cp.async 3-stage staging of 4-step groups into smem; compute reads smem.
// Block 128 = 16 wp x 8 ch-pairs. Grid (7, 8, b*2+dir).
// ---------------------------------------------------------------------------
#define SUH (4 * 3 * 16 * 16)   // halves per u stage (3072)
#define SXH (4 * 16 * 16)       // halves per x stage (1024)
__global__ void __launch_bounds__(128) k3_scan2(
    const float* __restrict__ wc2, const float* __restrict__ b2,
    float* __restrict__ out)
{
    __shared__ __half su[3][SUH];
    __shared__ __half sx[3][SXH];
    __shared__ float  hs[4][16][17];

    const int tid = threadIdx.x;
    const int tcp = tid & 7;           // ch-pair within group
    const int tw  = tid >> 3;          // wp within group (0..15)
    const int bz  = blockIdx.z;
    const int b   = bz >> 1;
    const int dir = bz & 1;
    const int wpB = blockIdx.x * 16;   // wp base
    const int ch0 = dir * D + blockIdx.y * 16;     // channel base (16 wide)
    const int ch  = ch0 + tcp * 2;

    const float2 vf = *(const float2*)(wc2 + ch);
    const float2 vr = *(const float2*)(wc2 + 256 + ch);
    const float2 bf = *(const float2*)(b2 + ch);
    const float2 br = *(const float2*)(b2 + 256 + ch);
    const float SC = 1.41421356237309515f;

    const int l0 = dir ? (L - 1) : 0;
    const int dl = dir ? -1 : 1;

    const int ow = tid & 15;
    const int oc = tid >> 4;   // 0..7 (handles oc and oc+8)
    float* ob0 = out + ((size_t)(b * 256 + dir * D + blockIdx.y * 16 + oc) * HP) * HP
                     + wpB + ow;
    float* ob1 = out + ((size_t)(b * 256 + dir * D + blockIdx.y * 16 + oc + 8) * HP) * HP
                     + wpB + ow;

    // ---- group loader: 3 u-chunks + 1 x-chunk per thread (16B each) ----
    // u chunk c (0..383): s=c/96, j=(c%96)>>5, wp=(c>>1)&15, h=c&1
    const int uc_s[3]  = { (tid + 0) / 96, (tid + 128) / 96, (tid + 256) / 96 };
    const int uc_j[3]  = { ((tid + 0) % 96) >> 5, ((tid + 128) % 96) >> 5, ((tid + 256) % 96) >> 5 };
    const int uc_wp    = (tid >> 1) & 15;          // same for all 3 (c>>1 &15 differs! careful)
    // NOTE: wp differs per chunk: recompute per q below.

#define K3_LOAD_GROUP(gg, st)                                                        \
    do {                                                                             \
        _Pragma("unroll")                                                            \
        for (int q = 0; q < 3; q++) {                                                \
            const int c  = tid + q * 128;                                            \
            const int s  = c / 96;                                                   \
            const int r  = c % 96;                                                   \
            const int j  = r >> 5;                                                   \
            const int wp = (r >> 1) & 15;                                            \
            const int h  = c & 1;                                                    \
            const int l  = l0 + dl * ((gg) * 4 + s);                                 \
            const __half* gp = g_u2h                                                 \
                + ((size_t)l * NSEQ + (size_t)(wpB + wp) * 8 + b) * 768              \
                + ch0 + j * 256 + h * 8;                                             \
            const unsigned sm = (unsigned)__cvta_generic_to_shared(                  \
                &su[st][(((s * 3 + j) * 16 + wp) * 16) + h * 8]);                    \
            CP16(sm, gp);                                                            \
        }                                                                            \
        {                                                                            \
            const int s  = tid >> 5;                                                 \
            const int wp = (tid >> 1) & 15;                                          \
            const int h  = tid & 1;                                                  \
            const int l  = l0 + dl * ((gg) * 4 + s);                                 \
            const __half* gp = g_a2h                                                 \
                + ((size_t)l * NSEQ + (size_t)(wpB + wp) * 8 + b) * 256              \
                + ch0 + h * 8;                                                       \
            const unsigned sm = (unsigned)__cvta_generic_to_shared(                  \
                &sx[st][((s * 16 + wp) * 16) + h * 8]);                              \
            CP16(sm, gp);                                                            \
        }                                                                            \
        CP_COMMIT();                                                                 \
    } while (0)

    (void)uc_s; (void)uc_j; (void)uc_wp;

    // prologue: groups 0,1
    K3_LOAD_GROUP(0, 0);
    K3_LOAD_GROUP(1, 1);

    float2 cst = make_float2(0.f, 0.f);
    for (int g = 0; g < 28; g++) {
        if (g == 27) { CP_WAIT0(); } else { CP_WAIT1(); }
        __syncthreads();
        if (g < 26) K3_LOAD_GROUP(g + 2, (g + 2) % 3);

        const int st = g % 3;
#pragma unroll
        for (int j = 0; j < 4; j++) {
            const int rb = (j * 3) * 16 + tw;   // base row for this step
            const float2 u0  = __half22float2(*(const __half2*)&su[st][(rb)*16 + tcp * 2]);
            const float2 u1  = __half22float2(*(const __half2*)&su[st][(rb + 16) * 16 + tcp * 2]);
            const float2 u2v = __half22float2(*(const __half2*)&su[st][(rb + 32) * 16 + tcp * 2]);
            const float2 xp  = __half22float2(*(const __half2*)&sx[st][(j * 16 + tw) * 16 + tcp * 2]);
            const float fg0 = sigmoidf_(u1.x + vf.x * cst.x + bf.x);
            const float fg1 = sigmoidf_(u1.y + vf.y * cst.y + bf.y);
            cst.x = fg0 * (cst.x - u0.x) + u0.x;
            cst.y = fg1 * (cst.y - u0.y) + u0.y;
            const float rg0 = sigmoidf_(u2v.x + vr.x * cst.x + br.x);
            const float rg1 = sigmoidf_(u2v.y + vr.y * cst.y + br.y);
            const float x0 = xp.x * SC, x1 = xp.y * SC;
            hs[j][tcp * 2][tw]     = rg0 * (cst.x - x0) + x0;
            hs[j][tcp * 2 + 1][tw] = rg1 * (cst.y - x1) + x1;
        }
        __syncthreads();
#pragma unroll
        for (int j = 0; j < 4; j++) {
            const int l = l0 + dl * (g * 4 + j);
            ob0[(size_t)l * HP] = hs[j][oc][ow];
            ob1[(size_t)l * HP] = hs[j][oc + 8][ow];
        }
    }
}

// ---------------------------------------------------------------------------
extern "C" void kernel_launch(void* const* d_in, const int* in_sizes, int n_in,
                              void* d_out, int out_size)
{
    const float* x   = (const float*)d_in[0];
    const float* W1  = (const float*)d_in[1];
    const float* wc1 = (const float*)d_in[2];
    const float* b1  = (const float*)d_in[3];
    const float* W2  = (const float*)d_in[4];
    const float* wc2 = (const float*)d_in[5];
    const float* b2  = (const float*)d_in[6];
    float* out = (float*)d_out;

    cudaFuncSetAttribute(k2_gemm_f16, cudaFuncAttributeMaxDynamicSharedMemorySize,
                         6 * STGB);

    k0_w2half<<<768, 256>>>(W2);
    k1_scan1<<<dim3(NSEQ, 2), 128>>>(x, W1, wc1, b1);
    k2_gemm_f16<<<dim3(768 / 128, M_TOT / 128), 256, 6 * STGB>>>();
    k3_scan2<<<dim3(HP / 16, 128 / 16, 16), 128>>>(wc2, b2, out);
}

// round 12
// speedup vs baseline: 1.0690x; 1.0690x over previous
#include <cuda_runtime.h>
#include <cuda_fp16.h>
#include <cstdint>
#include <cmath>

// Problem constants
#define BATCH 8
#define CHN 3
#define IMG 224
#define HP 112      // Hp = Wp = 112
#define FIN 12      // patch features
#define D 128       // hidden per direction
#define L 112       // scan length (both stages)
#define NSEQ 896    // Hp*B = Wp*B
#define M_TOT (L * NSEQ)   // 100352

// Scratch (device globals — no dynamic allocation allowed)
__device__ __half g_a2h[(size_t)M_TOT * 256];   // stage-1 out (half): GEMM A + k3 xprime
__device__ __half g_w2t[(size_t)768 * 256];     // W2 transposed+permuted [j*256+ch][k], half
__device__ __half g_u2h[(size_t)M_TOT * 768];   // GEMM out, cols j*256+ch (j-major)

__device__ __forceinline__ float sigmoidf_(float v) {
    float t;
    asm("tanh.approx.f32 %0, %1;" : "=f"(t) : "f"(v * 0.5f));
    return fmaf(t, 0.5f, 0.5f);
}

typedef unsigned long long u64t;
__device__ __forceinline__ u64t pack2(float a, float b) {
    u64t r; asm("mov.b64 %0,{%1,%2};" : "=l"(r) : "f"(a), "f"(b)); return r;
}
__device__ __forceinline__ u64t fma2(u64t a, u64t b, u64t c) {
    u64t d; asm("fma.rn.f32x2 %0,%1,%2,%3;" : "=l"(d) : "l"(a), "l"(b), "l"(c)); return d;
}
__device__ __forceinline__ void unpack2(u64t v, float& a, float& b) {
    asm("mov.b64 {%0,%1},%2;" : "=f"(a), "=f"(b) : "l"(v));
}

#define LDSM4(r0, r1, r2, r3, addr) \
    asm volatile("ldmatrix.sync.aligned.m8n8.x4.shared.b16 {%0,%1,%2,%3},[%4];" \
                 : "=r"(r0), "=r"(r1), "=r"(r2), "=r"(r3) : "r"(addr))
#define CP16(sm, gp) \
    asm volatile("cp.async.cg.shared.global [%0], [%1], 16;" :: "r"(sm), "l"(gp))
#define CP_COMMIT() asm volatile("cp.async.commit_group;")
#define CP_WAIT1()  asm volatile("cp.async.wait_group 1;")
#define CP_WAIT0()  asm volatile("cp.async.wait_group 0;")

// ---------------------------------------------------------------------------
// Kernel 1: fused W2->half transpose (dir0 blocks) + patch-extract + (x @ W1)
// + bidirectional SRU scan (k=4). f-paired fma2 projection.
// ---------------------------------------------------------------------------
__global__ void __launch_bounds__(128) k1_scan1(
    const float* __restrict__ x, const float* __restrict__ W1,
    const float* __restrict__ wc1, const float* __restrict__ b1,
    const float* __restrict__ W2)
{
    const int n1  = blockIdx.x;        // hp*8 + b
    const int dir = blockIdx.y;
    const int d   = threadIdx.x;       // 0..127 (output channel)
    const int lid = d & 31;
    const int hp  = n1 >> 3;
    const int b   = n1 & 7;

    // --- merged k0: W2[k][n] f32 -> g_w2t[(n%3)*256+n/3][k] half ---
    if (dir == 0 && n1 < 768) {
#pragma unroll
        for (int q = 0; q < 2; q++) {
            const int idx = n1 * 256 + q * 128 + d;    // k*768 + n
            const int k = idx / 768;
            const int n = idx % 768;
            const int np = (n % 3) * 256 + n / 3;
            g_w2t[(size_t)np * 256 + k] = __float2half(W2[idx]);
        }
    }

    // weights: f-paired, per output j: wp2[j][fp] = (w[2fp][j], w[2fp+1][j])
    u64t wp2[4][FIN / 2];
    const int col0 = (dir * D + d) * 4;
#pragma unroll
    for (int fp = 0; fp < FIN / 2; fp++) {
#pragma unroll
        for (int j = 0; j < 4; j++) {
            wp2[j][fp] = pack2(W1[(2 * fp) * 1024 + col0 + j],
                               W1[(2 * fp + 1) * 1024 + col0 + j]);
        }
    }
    const int chg = dir * D + d;
    const float vf = wc1[chg];
    const float vr = wc1[256 + chg];
    const float bf = b1[chg];
    const float br = b1[256 + chg];

    const int l0 = dir ? (L - 1) : 0;
    const int dl = dir ? -1 : 1;

    int xrowbase = 0, xww = 0;
    float nv = 0.0f;
    if (lid < FIN) {
        int c  = lid >> 2;
        int wh = (lid >> 1) & 1;
        xww    = lid & 1;
        xrowbase = ((b * 3 + c) * IMG + 2 * hp + wh) * IMG;
        nv = x[xrowbase + 2 * l0 + xww];
    }

    size_t oidx = ((size_t)hp * NSEQ + l0 * 8 + b) * 256 + chg;
    const ptrdiff_t ostep = (ptrdiff_t)dl * 8 * 256;

    float cst = 0.0f;
    for (int s = 0; s < L; s++) {
        const float cv = nv;
        if (lid < FIN && (s + 1) < L) {
            nv = x[xrowbase + 2 * (l0 + dl * (s + 1)) + xww];
        }
        // broadcast p and pack feature-pairs (6 packs, shared by all 4 j)
        u64t pp[FIN / 2];
#pragma unroll
        for (int fp = 0; fp < FIN / 2; fp++) {
            const float pa = __shfl_sync(0xffffffffu, cv, 2 * fp);
            const float pb = __shfl_sync(0xffffffffu, cv, 2 * fp + 1);
            pp[fp] = pack2(pa, pb);
        }
        u64t a0 = 0ull, a1 = 0ull, a2 = 0ull, a3 = 0ull;
#pragma unroll
        for (int fp = 0; fp < FIN / 2; fp++) {
            a0 = fma2(pp[fp], wp2[0][fp], a0);
            a1 = fma2(pp[fp], wp2[1][fp], a1);
            a2 = fma2(pp[fp], wp2[2][fp], a2);
            a3 = fma2(pp[fp], wp2[3][fp], a3);
        }
        float x0, y0, x1, y1, x2, y2, x3, y3;
        unpack2(a0, x0, y0);
        unpack2(a1, x1, y1);
        unpack2(a2, x2, y2);
        unpack2(a3, x3, y3);
        const float u0 = x0 + y0;
        const float u1 = x1 + y1;
        const float u2 = x2 + y2;
        const float u3 = x3 + y3;

        const float fg = sigmoidf_(u1 + vf * cst + bf);
        cst = fg * (cst - u0) + u0;
        const float rg = sigmoidf_(u2 + vr * cst + br);
        const float h  = rg * (cst - u3) + u3;
        g_a2h[oidx] = __float2half(h);
        oidx += ostep;
    }
}

// ---------------------------------------------------------------------------
// Kernel 2: fp16 GEMM  U2[100352,768] = a2h @ w2t^T
// BM=128, BN=128, BK=32; 256 threads; warp tile 32x64; ldmatrix + m16n8k16.
// cp.async 3-stage pipeline (dynamic smem, 60KB). [R8 config — HMMA wall]
// ---------------------------------------------------------------------------
#define SAH 40                      // halves per smem row (80B, LDSM conflict-free)
#define STGB (128 * SAH * 2)        // bytes per stage per matrix (10240)
__global__ void __launch_bounds__(256, 2) k2_gemm_f16()
{
    extern __shared__ char k2smem[];
    __half* As = (__half*)k2smem;                 // 3 stages
    __half* Bs = (__half*)(k2smem + 3 * STGB);    // 3 stages

    const int tid  = threadIdx.x;
    const int lane = tid & 31;
    const int gid  = lane >> 2;     // 0..7
    const int tig  = lane & 3;      // 0..3
    const int warp = tid >> 5;
    const int wm   = (warp & 3) * 32;   // warp m offset
    const int wn   = (warp >> 2) * 64;  // warp n offset
    const int n0   = blockIdx.x * 128;
    const int m0   = blockIdx.y * 128;

    const int row = tid >> 1;           // 0..127
    const int kc  = (tid & 1) * 16;     // half-offset within 32-wide ktile

    const __half* Ag = g_a2h + (size_t)(m0 + row) * 256 + kc;
    const __half* Bg = g_w2t + (size_t)(n0 + row) * 256 + kc;

    const unsigned sa = (unsigned)__cvta_generic_to_shared(As + row * SAH + kc);
    const unsigned sb = (unsigned)__cvta_generic_to_shared(Bs + row * SAH + kc);

    // ldmatrix base addresses (stage 0, kk = 0)
    const unsigned aAddr = (unsigned)__cvta_generic_to_shared(As)
        + (((wm + (lane & 7) + (lane & 8)) * SAH + ((lane & 16) ? 8 : 0)) * 2);
    const unsigned bAddr = (unsigned)__cvta_generic_to_shared(Bs)
        + (((wn + (lane & 7) + ((lane & 16) ? 8 : 0)) * SAH + ((lane & 8) ? 8 : 0)) * 2);

    // prologue: stages 0,1 (ktiles 0,1)
#pragma unroll
    for (int s = 0; s < 2; s++) {
        CP16(sa + s * STGB,      Ag + s * 32);
        CP16(sa + s * STGB + 16, Ag + s * 32 + 8);
        CP16(sb + s * STGB,      Bg + s * 32);
        CP16(sb + s * STGB + 16, Bg + s * 32 + 8);
        CP_COMMIT();
    }

    float c[2][8][4];
#pragma unroll
    for (int mi = 0; mi < 2; mi++)
#pragma unroll
        for (int ni = 0; ni < 8; ni++)
#pragma unroll
            for (int j = 0; j < 4; j++) c[mi][ni][j] = 0.f;

    for (int kt = 0; kt < 8; kt++) {
        if (kt == 7) { CP_WAIT0(); } else { CP_WAIT1(); }
        __syncthreads();

        if (kt < 6) {
            const int s  = (kt + 2) % 3;
            const int k0 = (kt + 2) * 32;
            CP16(sa + s * STGB,      Ag + k0);
            CP16(sa + s * STGB + 16, Ag + k0 + 8);
            CP16(sb + s * STGB,      Bg + k0);
            CP16(sb + s * STGB + 16, Bg + k0 + 8);
            CP_COMMIT();
        }

        const unsigned aB = aAddr + (kt % 3) * STGB;
        const unsigned bB = bAddr + (kt % 3) * STGB;
#pragma unroll
        for (int kk = 0; kk < 32; kk += 16) {
            unsigned a[2][4];
#pragma unroll
            for (int mi = 0; mi < 2; mi++)
                LDSM4(a[mi][0], a[mi][1], a[mi][2], a[mi][3],
                      aB + mi * (16 * SAH * 2) + kk * 2);
#pragma unroll
            for (int nt = 0; nt < 4; nt++) {
                unsigned b00, b01, b10, b11;
                LDSM4(b00, b01, b10, b11, bB + nt * (16 * SAH * 2) + kk * 2);
#pragma unroll
                for (int mi = 0; mi < 2; mi++) {
                    asm volatile(
                        "mma.sync.aligned.m16n8k16.row.col.f32.f16.f16.f32 "
                        "{%0,%1,%2,%3}, {%4,%5,%6,%7}, {%8,%9}, {%0,%1,%2,%3};"
                        : "+f"(c[mi][2 * nt][0]), "+f"(c[mi][2 * nt][1]),
                          "+f"(c[mi][2 * nt][2]), "+f"(c[mi][2 * nt][3])
                        : "r"(a[mi][0]), "r"(a[mi][1]), "r"(a[mi][2]), "r"(a[mi][3]),
                          "r"(b00), "r"(b01));
                    asm volatile(
                        "mma.sync.aligned.m16n8k16.row.col.f32.f16.f16.f32 "
                        "{%0,%1,%2,%3}, {%4,%5,%6,%7}, {%8,%9}, {%0,%1,%2,%3};"
                        : "+f"(c[mi][2 * nt + 1][0]), "+f"(c[mi][2 * nt + 1][1]),
                          "+f"(c[mi][2 * nt + 1][2]), "+f"(c[mi][2 * nt + 1][3])
                        : "r"(a[mi][0]), "r"(a[mi][1]), "r"(a[mi][2]), "r"(a[mi][3]),
                          "r"(b10), "r"(b11));
                }
            }
        }
    }

#pragma unroll
    for (int mi = 0; mi < 2; mi++) {
#pragma unroll
        for (int ni = 0; ni < 8; ni++) {
            const int r0  = m0 + wm + mi * 16 + gid;
            const int col = n0 + wn + ni * 8 + tig * 2;
            *(__half2*)(g_u2h + (size_t)r0 * 768 + col) =
                __floats2half2_rn(c[mi][ni][0], c[mi][ni][1]);
            *(__half2*)(g_u2h + (size_t)(r0 + 8) * 768 + col) =
                __floats2half2_rn(c[mi][ni][2], c[mi][ni][3]);
        }
    }
}

// ---------------------------------------------------------------------------
// Kernel 3: bidirectional SRU scan (k=3) + coalesced output, sw-pipelined,
// half2 channel-pairs, 4-step groups (reg-slim). Block 128 = 16 wp x 8 pairs.
// [R10 config]
// ---------------------------------------------------------------------------
__global__ void __launch_bounds__(128) k3_scan2(
    const float* __restrict__ wc2, const float* __restrict__ b2,
    float* __restrict__ out)
{
    const int tid = threadIdx.x;
    const int tcp = tid & 7;           // ch-pair within group
    const int tw  = tid >> 3;          // wp within group (0..15)
    const int bz  = blockIdx.z;
    const int b   = bz >> 1;
    const int dir = bz & 1;
    const int wp  = blockIdx.x * 16 + tw;
    const int cg  = blockIdx.y * 16 + tcp * 2;     // even channel index
    const int ch  = dir * D + cg;
    const int n2  = wp * 8 + b;

    const float2 vf = *(const float2*)(wc2 + ch);
    const float2 vr = *(const float2*)(wc2 + 256 + ch);
    const float2 bf = *(const float2*)(b2 + ch);
    const float2 br = *(const float2*)(b2 + 256 + ch);
    const float SC = 1.41421356237309515f;

    const int l0 = dir ? (L - 1) : 0;
    const int dl = dir ? -1 : 1;

    __shared__ float hs[4][16][17];

    const int ow = tid & 15;
    const int oc = tid >> 4;   // 0..7 (handles oc and oc+8)
    float* ob0 = out + ((size_t)(b * 256 + dir * D + blockIdx.y * 16 + oc) * HP) * HP
                     + blockIdx.x * 16 + ow;
    float* ob1 = out + ((size_t)(b * 256 + dir * D + blockIdx.y * 16 + oc + 8) * HP) * HP
                     + blockIdx.x * 16 + ow;

    const ptrdiff_t ustep = (ptrdiff_t)dl * (NSEQ * 768 / 2);   // half2 units
    const ptrdiff_t astep = (ptrdiff_t)dl * (NSEQ * 256 / 2);
    const __half2* ub = (const __half2*)(g_u2h + ((size_t)l0 * NSEQ + n2) * 768 + ch);
    const __half2* ab = (const __half2*)(g_a2h + ((size_t)l0 * NSEQ + n2) * 256 + ch);

    __half2 cu0[4], cu1[4], cu2[4], cxp[4];
    __half2 pu0[4], pu1[4], pu2[4], pxp[4];

#pragma unroll
    for (int j = 0; j < 4; j++) {
        const __half2* up = ub + (ptrdiff_t)j * ustep;
        cu0[j] = up[0];
        cu1[j] = up[128];
        cu2[j] = up[256];
        cxp[j] = ab[(ptrdiff_t)j * astep];
    }

    float2 cst = make_float2(0.f, 0.f);
#pragma unroll 2
    for (int g = 0; g < 28; g++) {
        if (g < 27) {
#pragma unroll
            for (int j = 0; j < 4; j++) {
                const int s = (g + 1) * 4 + j;
                const __half2* up = ub + (ptrdiff_t)s * ustep;
                pu0[j] = up[0];
                pu1[j] = up[128];
                pu2[j] = up[256];
                pxp[j] = ab[(ptrdiff_t)s * astep];
            }
        }
#pragma unroll
        for (int j = 0; j < 4; j++) {
            const float2 u0  = __half22float2(cu0[j]);
            const float2 u1  = __half22float2(cu1[j]);
            const float2 u2v = __half22float2(cu2[j]);
            const float2 xp  = __half22float2(cxp[j]);
            const float fg0 = sigmoidf_(u1.x + vf.x * cst.x + bf.x);
            const float fg1 = sigmoidf_(u1.y + vf.y * cst.y + bf.y);
            cst.x = fg0 * (cst.x - u0.x) + u0.x;
            cst.y = fg1 * (cst.y - u0.y) + u0.y;
            const float rg0 = sigmoidf_(u2v.x + vr.x * cst.x + br.x);
            const float rg1 = sigmoidf_(u2v.y + vr.y * cst.y + br.y);
            const float x0 = xp.x * SC, x1 = xp.y * SC;
            hs[j][tcp * 2][tw]     = rg0 * (cst.x - x0) + x0;
            hs[j][tcp * 2 + 1][tw] = rg1 * (cst.y - x1) + x1;
        }
        __syncthreads();
#pragma unroll
        for (int j = 0; j < 4; j++) {
            const int l = l0 + dl * (g * 4 + j);
            ob0[(size_t)l * HP] = hs[j][oc][ow];
            ob1[(size_t)l * HP] = hs[j][oc + 8][ow];
        }
        __syncthreads();
#pragma unroll
        for (int j = 0; j < 4; j++) {
            cu0[j] = pu0[j];
            cu1[j] = pu1[j];
            cu2[j] = pu2[j];
            cxp[j] = pxp[j];
        }
    }
}

// ---------------------------------------------------------------------------
extern "C" void kernel_launch(void* const* d_in, const int* in_sizes, int n_in,
                              void* d_out, int out_size)
{
    const float* x   = (const float*)d_in[0];
    const float* W1  = (const float*)d_in[1];
    const float* wc1 = (const float*)d_in[2];
    const float* b1  = (const float*)d_in[3];
    const float* W2  = (const float*)d_in[4];
    const float* wc2 = (const float*)d_in[5];
    const float* b2  = (const float*)d_in[6];
    float* out = (float*)d_out;

    cudaFuncSetAttribute(k2_gemm_f16, cudaFuncAttributeMaxDynamicSharedMemorySize,
                         6 * STGB);

    k1_scan1<<<dim3(NSEQ, 2), 128>>>(x, W1, wc1, b1, W2);
    k2_gemm_f16<<<dim3(768 / 128, M_TOT / 128), 256, 6 * STGB>>>();
    k3_scan2<<<dim3(HP / 16, 128 / 16, 16), 128>>>(wc2, b2, out);
}